// round 4
// baseline (speedup 1.0000x reference)
#include <cuda_runtime.h>
#include <cuda_bf16.h>
#include <cstdint>

#define NR 131072
#define DD 128
#define KK 1024
#define TM 128
#define PAD 136                 // bf16 elems per padded row (272 B)

typedef unsigned long long ull;

// ---------------- device scratch (static; no runtime alloc) ----------------
__device__ int   g_idx[NR];
__device__ float g_sums[DD * KK];
__device__ float g_lossb[256];
__device__ float g_eT[KK * DD];        // e^T [K][D] fp32
__device__ __nv_bfloat16 g_eThi[KK * DD];
__device__ __nv_bfloat16 g_eTlo[KK * DD];
__device__ float g_cnorm[KK];
__device__ int   g_nflag;
__device__ int   g_flag[NR];
__device__ int   g_icnt[KK];
__device__ int   g_off[KK];
__device__ int   g_cur[KK];
__device__ int   g_perm[NR];

// ---------------- smem layout (bytes) ----------------
#define AHALF   34816            /* 128*PAD*2 */
#define SM_B0   0                /* also A staging: hi|lo : 69632 */
#define SM_B1   69632
#define SM_CN   139264           /* 1024 fp32 */
#define SM_TOTAL 143360

#define TAU_D 1.5e-2f

// ---------------- helpers ----------------
__device__ __forceinline__ uint32_t smem_u32(const void* p) {
    uint32_t a;
    asm("{ .reg .u64 t; cvta.to.shared.u64 t, %1; cvt.u32.u64 %0, t; }"
        : "=r"(a) : "l"(p));
    return a;
}
__device__ __forceinline__ void cp_async16(uint32_t dst, const void* src) {
    asm volatile("cp.async.cg.shared.global [%0], [%1], 16;"
                 :: "r"(dst), "l"(src) : "memory");
}
__device__ __forceinline__ void cp_commit() {
    asm volatile("cp.async.commit_group;" ::: "memory");
}
__device__ __forceinline__ void cp_wait0() {
    asm volatile("cp.async.wait_group 0;" ::: "memory");
}
__device__ __forceinline__ void cp_wait1() {
    asm volatile("cp.async.wait_group 1;" ::: "memory");
}
__device__ __forceinline__ void ldsm4(uint32_t& r0, uint32_t& r1, uint32_t& r2,
                                      uint32_t& r3, uint32_t addr) {
    asm volatile("ldmatrix.sync.aligned.m8n8.x4.shared.b16 {%0,%1,%2,%3}, [%4];"
                 : "=r"(r0), "=r"(r1), "=r"(r2), "=r"(r3) : "r"(addr));
}
__device__ __forceinline__ void mma_bf16(float& d0, float& d1, float& d2, float& d3,
                                         uint32_t a0, uint32_t a1, uint32_t a2, uint32_t a3,
                                         uint32_t b0, uint32_t b1) {
    asm volatile("mma.sync.aligned.m16n8k16.row.col.f32.bf16.bf16.f32 "
                 "{%0,%1,%2,%3}, {%4,%5,%6,%7}, {%8,%9}, {%0,%1,%2,%3};"
                 : "+f"(d0), "+f"(d1), "+f"(d2), "+f"(d3)
                 : "r"(a0), "r"(a1), "r"(a2), "r"(a3), "r"(b0), "r"(b1));
}
#define MMA4(accf, A, b0, b1) \
    mma_bf16(accf[0], accf[1], accf[2], accf[3], A[0], A[1], A[2], A[3], b0, b1)

// ---------------- prep kernels ----------------
__global__ void zero_kernel() {
    int i = blockIdx.x * 256 + threadIdx.x;
    if (i < KK)  g_icnt[i] = 0;
    if (i < 256) g_lossb[i] = 0.f;
    if (i == 0)  g_nflag = 0;
}

__global__ void transpose_kernel(const float* __restrict__ emb) {
    __shared__ float t[32][33];
    int kb = blockIdx.x * 32, db = blockIdx.y * 32;
    int tx = threadIdx.x, ty = threadIdx.y;
    #pragma unroll
    for (int r = ty; r < 32; r += 8)
        t[r][tx] = emb[(size_t)(db + r) * KK + kb + tx];
    __syncthreads();
    #pragma unroll
    for (int r = ty; r < 32; r += 8)
        g_eT[(size_t)(kb + r) * DD + db + tx] = t[tx][r];
}

__global__ void esplit_kernel() {
    int i = blockIdx.x * 256 + threadIdx.x;
    float v = g_eT[i];
    __nv_bfloat16 h = __float2bfloat16(v);
    g_eThi[i] = h;
    g_eTlo[i] = __float2bfloat16(v - __bfloat162float(h));
}

__global__ void cnorm_kernel(const float* __restrict__ emb) {
    int k = blockIdx.x * 256 + threadIdx.x;
    float s = 0.f;
    #pragma unroll 8
    for (int d = 0; d < DD; d++) {
        float e = emb[(size_t)d * KK + k];
        s = fmaf(e, e, s);
    }
    g_cnorm[k] = s;
}

// ---------------- HMMA bf16-split argmin (A in regs, ldmatrix B) ----------------
__global__ void __launch_bounds__(256, 1)
argmin_mma_kernel(const float* __restrict__ x) {
    extern __shared__ __align__(16) char smem[];
    const int tid = threadIdx.x;
    const int wid = tid >> 5, lane = tid & 31;
    const int g = lane >> 2, tg = lane & 3;
    const int m8 = lane >> 3, r8 = lane & 7;
    const int row0 = blockIdx.x * TM;
    const uint32_t sb = smem_u32(smem);

    // ---- stage A (x rows) into SM_B0 region, split hi/lo ----
    #pragma unroll
    for (int it = 0; it < 8; it++) {
        int c = it * 256 + tid;            // 0..2047
        int r = c >> 4, c8 = c & 15;
        const float4* src = (const float4*)(x + (size_t)(row0 + r) * DD + c8 * 8);
        float4 a = src[0], b = src[1];
        float vals[8] = {a.x, a.y, a.z, a.w, b.x, b.y, b.z, b.w};
        unsigned hs[8], ls[8];
        #pragma unroll
        for (int j = 0; j < 8; j++) {
            __nv_bfloat16 hb = __float2bfloat16(vals[j]);
            hs[j] = __bfloat16_as_ushort(hb);
            ls[j] = __bfloat16_as_ushort(__float2bfloat16(vals[j] - __bfloat162float(hb)));
        }
        uint4 ph, pl;
        ph.x = hs[0] | (hs[1] << 16); ph.y = hs[2] | (hs[3] << 16);
        ph.z = hs[4] | (hs[5] << 16); ph.w = hs[6] | (hs[7] << 16);
        pl.x = ls[0] | (ls[1] << 16); pl.y = ls[2] | (ls[3] << 16);
        pl.z = ls[4] | (ls[5] << 16); pl.w = ls[6] | (ls[7] << 16);
        int off = r * (PAD * 2) + c8 * 16;
        *(uint4*)(smem + SM_B0 + off)         = ph;
        *(uint4*)(smem + SM_B0 + AHALF + off) = pl;
    }
    __syncthreads();

    // ---- extract A fragments into registers (per warp: rows wid*16..wid*16+15) ----
    uint32_t ah[8][4], al[8][4];
    {
        const int rw = wid * 16;
        // A matrix mapping: row = rw + (m8&1)*8 + r8, colbase = (m8>>1)*8
        uint32_t base = sb + SM_B0 + (uint32_t)((rw + (m8 & 1) * 8 + r8) * (PAD * 2)
                                                + ((m8 >> 1) * 8) * 2);
        #pragma unroll
        for (int k = 0; k < 8; k++) {
            ldsm4(ah[k][0], ah[k][1], ah[k][2], ah[k][3], base + k * 32);
            ldsm4(al[k][0], al[k][1], al[k][2], al[k][3], base + AHALF + k * 32);
        }
    }
    // cnorm -> smem
    ((float4*)(smem + SM_CN))[tid] = ((const float4*)g_cnorm)[tid];
    __syncthreads();

    // ---- B tile 0 via cp.async (overwrites A staging; safe after sync) ----
    #pragma unroll
    for (int it = 0; it < 16; it++) {
        int i = it * 256 + tid;
        int half = i >> 11, r = (i >> 4) & 127, c8 = i & 15;
        const __nv_bfloat16* src = (half ? g_eTlo : g_eThi) + (size_t)r * DD + c8 * 8;
        cp_async16(sb + SM_B0 + half * AHALF + r * (PAD * 2) + c8 * 16, src);
    }
    cp_commit();

    float va1 = -3.4e38f, va2 = -3.4e38f, vb1 = -3.4e38f, vb2 = -3.4e38f;
    int ia1 = 0, ib1 = 0;
    const float* cns = (const float*)(smem + SM_CN);
    // B matrix mapping: rowadd = (m8>>1)*8 + r8, coladd = (m8&1)*8
    const uint32_t laneB = (uint32_t)(((m8 >> 1) * 8 + r8) * (PAD * 2) + (m8 & 1) * 16);

    for (int t = 0; t < 8; t++) {
        if (t < 7) {
            int nb = (t + 1) & 1;
            #pragma unroll
            for (int it = 0; it < 16; it++) {
                int i = it * 256 + tid;
                int half = i >> 11, r = (i >> 4) & 127, c8 = i & 15;
                const __nv_bfloat16* src =
                    (half ? g_eTlo : g_eThi) + (size_t)((t + 1) * 128 + r) * DD + c8 * 8;
                cp_async16(sb + (nb ? SM_B1 : SM_B0) + half * AHALF + r * (PAD * 2) + c8 * 16, src);
            }
            cp_commit();
            cp_wait1();
        } else {
            cp_wait0();
        }
        __syncthreads();

        const uint32_t bb = sb + ((t & 1) ? SM_B1 : SM_B0) + laneB;

        float acc[16][4];
        #pragma unroll
        for (int f = 0; f < 16; f++) {
            float c0 = -0.5f * cns[t * 128 + f * 8 + tg * 2];
            float c1 = -0.5f * cns[t * 128 + f * 8 + tg * 2 + 1];
            acc[f][0] = c0; acc[f][1] = c1; acc[f][2] = c0; acc[f][3] = c1;
        }

        #pragma unroll
        for (int k = 0; k < 8; k++) {
            #pragma unroll
            for (int p2 = 0; p2 < 8; p2++) {
                uint32_t bh0, bh1, bh2, bh3, bl0, bl1, bl2, bl3;
                uint32_t ab = bb + p2 * (16 * PAD * 2) + k * 32;
                ldsm4(bh0, bh1, bh2, bh3, ab);
                ldsm4(bl0, bl1, bl2, bl3, ab + AHALF);
                MMA4(acc[p2 * 2],     ah[k], bh0, bh1);
                MMA4(acc[p2 * 2],     ah[k], bl0, bl1);
                MMA4(acc[p2 * 2],     al[k], bh0, bh1);
                MMA4(acc[p2 * 2 + 1], ah[k], bh2, bh3);
                MMA4(acc[p2 * 2 + 1], ah[k], bl2, bl3);
                MMA4(acc[p2 * 2 + 1], al[k], bh2, bh3);
            }
        }

        #pragma unroll
        for (int f = 0; f < 16; f++) {
            int idx0 = t * 128 + f * 8 + tg * 2;
            float d;
            d = acc[f][0];
            if (d > va1) { va2 = va1; va1 = d; ia1 = idx0; } else if (d > va2) va2 = d;
            d = acc[f][1];
            if (d > va1) { va2 = va1; va1 = d; ia1 = idx0 + 1; } else if (d > va2) va2 = d;
            d = acc[f][2];
            if (d > vb1) { vb2 = vb1; vb1 = d; ib1 = idx0; } else if (d > vb2) vb2 = d;
            d = acc[f][3];
            if (d > vb1) { vb2 = vb1; vb1 = d; ib1 = idx0 + 1; } else if (d > vb2) vb2 = d;
        }
        __syncthreads();
    }

    // reduce across the 4 tg-lanes sharing each row
    #pragma unroll
    for (int off = 2; off; off >>= 1) {
        float ov1 = __shfl_down_sync(0xffffffffu, va1, off, 4);
        int   oi1 = __shfl_down_sync(0xffffffffu, ia1, off, 4);
        float ov2 = __shfl_down_sync(0xffffffffu, va2, off, 4);
        if (ov1 > va1 || (ov1 == va1 && oi1 < ia1)) {
            va2 = fmaxf(va1, ov2); va1 = ov1; ia1 = oi1;
        } else va2 = fmaxf(va2, ov1);
        ov1 = __shfl_down_sync(0xffffffffu, vb1, off, 4);
        oi1 = __shfl_down_sync(0xffffffffu, ib1, off, 4);
        ov2 = __shfl_down_sync(0xffffffffu, vb2, off, 4);
        if (ov1 > vb1 || (ov1 == vb1 && oi1 < ib1)) {
            vb2 = fmaxf(vb1, ov2); vb1 = ov1; ib1 = oi1;
        } else vb2 = fmaxf(vb2, ov1);
    }
    if (tg == 0) {
        int ra = row0 + wid * 16 + g, rb = ra + 8;
        g_idx[ra] = ia1;
        g_idx[rb] = ib1;
        if (va1 - va2 < TAU_D) { int s = atomicAdd(&g_nflag, 1); g_flag[s] = ra; }
        if (vb1 - vb2 < TAU_D) { int s = atomicAdd(&g_nflag, 1); g_flag[s] = rb; }
    }
}

// ---------------- exact fp32 rescore of flagged rows ----------------
__global__ void rescore_kernel(const float* __restrict__ x) {
    __shared__ float xs[8 * 128];
    __shared__ ull best[8];
    __shared__ int rows[8];
    int tid = threadIdx.x;
    int nflag = g_nflag;
    for (int base = blockIdx.x * 8; base < nflag; base += gridDim.x * 8) {
        int cnt = min(8, nflag - base);
        if (tid < cnt) { rows[tid] = g_flag[base + tid]; best[tid] = ~0ull; }
        __syncthreads();
        for (int i = tid; i < cnt * 128; i += 256)
            xs[i] = x[(size_t)rows[i >> 7] * DD + (i & 127)];
        __syncthreads();
        for (int k = tid; k < KK; k += 256) {
            float s[8];
            #pragma unroll
            for (int i = 0; i < 8; i++) s[i] = 0.f;
            const float4* e4 = (const float4*)(g_eT + (size_t)k * DD);
            const float4* x4 = (const float4*)xs;
            #pragma unroll 4
            for (int d4 = 0; d4 < 32; d4++) {
                float4 e = e4[d4];
                #pragma unroll
                for (int i = 0; i < 8; i++) {
                    float4 xv = x4[i * 32 + d4];
                    s[i] = fmaf(e.x, xv.x, s[i]);
                    s[i] = fmaf(e.y, xv.y, s[i]);
                    s[i] = fmaf(e.z, xv.z, s[i]);
                    s[i] = fmaf(e.w, xv.w, s[i]);
                }
            }
            float cn = g_cnorm[k];
            #pragma unroll
            for (int i = 0; i < 8; i++) {
                float dist = fmaf(-2.f, s[i], cn);
                unsigned u = __float_as_uint(dist);
                u ^= (u >> 31) ? 0xFFFFFFFFu : 0x80000000u;
                ull key = ((ull)u << 32) | (unsigned)k;
                atomicMin(&best[i], key);
            }
        }
        __syncthreads();
        if (tid < cnt) g_idx[rows[tid]] = (int)(best[tid] & 0xFFFFFFFFu);
        __syncthreads();
    }
}

// ---------------- counting-sort segment sums ----------------
__global__ void hist_kernel() {
    __shared__ int h[KK];
    int tid = threadIdx.x;
    for (int i = tid; i < KK; i += 512) h[i] = 0;
    __syncthreads();
    for (int n = blockIdx.x * 512 + tid; n < NR; n += gridDim.x * 512)
        atomicAdd(&h[g_idx[n]], 1);
    __syncthreads();
    for (int i = tid; i < KK; i += 512)
        if (h[i]) atomicAdd(&g_icnt[i], h[i]);
}

__global__ void scan_kernel() {
    __shared__ int s[KK];
    int tid = threadIdx.x;
    int v = g_icnt[tid];
    s[tid] = v;
    __syncthreads();
    for (int off = 1; off < KK; off <<= 1) {
        int t = (tid >= off) ? s[tid - off] : 0;
        __syncthreads();
        s[tid] += t;
        __syncthreads();
    }
    int excl = s[tid] - v;
    g_off[tid] = excl;
    g_cur[tid] = excl;
}

__global__ void rank_kernel() {
    int n = blockIdx.x * 256 + threadIdx.x;
    int k = g_idx[n];
    int pos = atomicAdd(&g_cur[k], 1);
    g_perm[pos] = n;
}

__global__ void sums_kernel(const float* __restrict__ x) {
    int k = blockIdx.x;
    int d = threadIdx.x;
    int st = g_off[k], cnt = g_icnt[k];
    const int* pm = g_perm + st;
    float acc = 0.f;
    int i = 0;
    for (; i + 4 <= cnt; i += 4) {
        int n0 = pm[i], n1 = pm[i + 1], n2 = pm[i + 2], n3 = pm[i + 3];
        float v0 = x[(size_t)n0 * DD + d];
        float v1 = x[(size_t)n1 * DD + d];
        float v2 = x[(size_t)n2 * DD + d];
        float v3 = x[(size_t)n3 * DD + d];
        acc += (v0 + v1) + (v2 + v3);
    }
    for (; i < cnt; i++) acc += x[(size_t)pm[i] * DD + d];
    g_sums[(size_t)d * KK + k] = acc;
}

// ---------------- q_st output + commitment loss ----------------
__global__ void qst_kernel(const float* __restrict__ x, float* __restrict__ outq) {
    int gid = blockIdx.x * 256 + threadIdx.x;
    int n = gid >> 5, dq = gid & 31, d0 = dq * 4;
    int k = g_idx[n];
    float4 xv = *(const float4*)(x + (size_t)n * DD + d0);
    float4 qv = *(const float4*)(g_eT + (size_t)k * DD + d0);
    float r0 = qv.x - xv.x, r1 = qv.y - xv.y, r2 = qv.z - xv.z, r3 = qv.w - xv.w;
    float4 o = make_float4(xv.x + r0, xv.y + r1, xv.z + r2, xv.w + r3);
    *(float4*)(outq + (size_t)n * DD + d0) = o;
    float ls = r0 * r0 + r1 * r1 + r2 * r2 + r3 * r3;

    __shared__ float wsum[8];
    #pragma unroll
    for (int off = 16; off; off >>= 1) ls += __shfl_down_sync(0xffffffffu, ls, off);
    if ((threadIdx.x & 31) == 0) wsum[threadIdx.x >> 5] = ls;
    __syncthreads();
    if (threadIdx.x < 8) {
        float t = wsum[threadIdx.x];
        #pragma unroll
        for (int off = 4; off; off >>= 1) t += __shfl_down_sync(0xffu, t, off);
        if (threadIdx.x == 0) atomicAdd(&g_lossb[blockIdx.x & 255], t);
    }
}

// ---------------- EMA finalize + loss ----------------
__global__ void finalize_kernel(const float* __restrict__ ema_count,
                                const float* __restrict__ emb_sum,
                                float* __restrict__ out, long long out_size) {
    long long base_q = (long long)NR * DD;
    if (out_size < base_q + 2LL * DD * KK + KK + 1) return;
    int i = blockIdx.x * 256 + threadIdx.x;
    float* out_emb  = out + base_q;
    float* out_cnt  = out_emb + DD * KK;
    float* out_sum  = out_cnt + KK;
    float* out_loss = out_sum + DD * KK;
    if (i < DD * KK) {
        int k = i & (KK - 1);
        float cnt = 0.15f * ema_count[k] + 0.85f * (float)g_icnt[k];
        float s   = 0.15f * emb_sum[i]   + 0.85f * g_sums[i];
        out_sum[i] = s;
        out_emb[i] = s / fmaxf(cnt, 1e-5f);
    }
    if (i < KK) out_cnt[i] = 0.15f * ema_count[i] + 0.85f * (float)g_icnt[i];
    if (i == 0) {
        float t = 0.f;
        for (int b = 0; b < 256; b++) t += g_lossb[b];
        *out_loss = t * (1.0f / ((float)NR * (float)DD));
    }
}

extern "C" void kernel_launch(void* const* d_in, const int* in_sizes, int n_in,
                              void* d_out, int out_size) {
    const float* x         = (const float*)d_in[0];
    const float* emb       = (const float*)d_in[1];
    const float* ema_count = (const float*)d_in[2];
    const float* emb_sum   = (const float*)d_in[3];
    float* out = (float*)d_out;

    cudaFuncSetAttribute(argmin_mma_kernel,
                         cudaFuncAttributeMaxDynamicSharedMemorySize, SM_TOTAL);

    zero_kernel<<<(KK + 255) / 256, 256>>>();
    transpose_kernel<<<dim3(KK / 32, DD / 32), dim3(32, 8)>>>(emb);
    cnorm_kernel<<<KK / 256, 256>>>(emb);
    esplit_kernel<<<KK * DD / 256, 256>>>();
    argmin_mma_kernel<<<NR / TM, 256, SM_TOTAL>>>(x);
    rescore_kernel<<<128, 256>>>(x);
    hist_kernel<<<148, 512>>>();
    scan_kernel<<<1, KK>>>();
    rank_kernel<<<NR / 256, 256>>>();
    sums_kernel<<<KK, DD>>>(x);
    qst_kernel<<<(NR * 32) / 256, 256>>>(x, out);
    finalize_kernel<<<(DD * KK + 255) / 256, 256>>>(ema_count, emb_sum, out,
                                                    (long long)out_size);
}